// round 2
// baseline (speedup 1.0000x reference)
#include <cuda_runtime.h>

#define Nn 100000
#define Ee 1600000
#define Gg 128
#define Hh 128
#define Cc 10
#define EPSf 1e-5f

// ---------------- scratch (device globals; no allocations allowed) -----------
__device__ float g_deg[Nn];
__device__ float g_dis[Nn];
__device__ float g_hW [Nn * Hh];   // h @ W
__device__ float g_agg[Nn * Hh];   // aggregated messages (pre-BN)
__device__ float g_sum[Hh];
__device__ float g_sumsq[Hh];
__device__ float g_scale[Hh];
__device__ float g_shift[Hh];
__device__ float g_pool[Gg * Hh];
__device__ int   g_src[Ee];
__device__ int   g_dst[Ee];
__device__ int   g_batch[Nn];
__device__ int   g_flag[2];        // [0]: edge_index is int64, [1]: batch is int64

// ---------------- dtype detection + canonicalization -------------------------
// For int64 buffers holding small non-negative values, every odd 32-bit word
// is 0. For int32 buffers the sampled words are node ids / tail graph ids
// (never all zero). Reads stay within the int32-sized footprint (safe for both).
__global__ void k_detect(const int* __restrict__ ei_w, const int* __restrict__ b_w) {
    if (threadIdx.x != 0) return;
    int all0 = 1;
    for (int i = 0; i < 16; i++)
        if (ei_w[2 * Ee - 1 - 2 * i] != 0) { all0 = 0; break; }
    g_flag[0] = all0;
    all0 = 1;
    for (int i = 0; i < 16; i++)
        if (b_w[Nn - 1 - 2 * i] != 0) { all0 = 0; break; }
    g_flag[1] = all0;
}

__global__ void k_cvt_edges(const int* __restrict__ w) {
    int e = blockIdx.x * blockDim.x + threadIdx.x;
    if (e >= Ee) return;
    if (g_flag[0]) {  // int64 layout: src at word 2e, dst at word 2*Ee + 2e
        g_src[e] = w[2 * e];
        g_dst[e] = w[2 * Ee + 2 * e];
    } else {
        g_src[e] = w[e];
        g_dst[e] = w[Ee + e];
    }
}

__global__ void k_cvt_batch(const int* __restrict__ w) {
    int i = blockIdx.x * blockDim.x + threadIdx.x;
    if (i >= Nn) return;
    g_batch[i] = g_flag[1] ? w[2 * i] : w[i];
}

// ---------------- degree / normalization ------------------------------------
__global__ void k_init_deg() {
    int i = blockIdx.x * blockDim.x + threadIdx.x;
    if (i < Nn) g_deg[i] = 1.0f;   // self-loop contributes 1
}

__global__ void k_count_deg() {
    int e = blockIdx.x * blockDim.x + threadIdx.x;
    if (e < Ee) atomicAdd(&g_deg[g_dst[e]], 1.0f);
}

__global__ void k_dis() {
    int i = blockIdx.x * blockDim.x + threadIdx.x;
    if (i < Nn) g_dis[i] = rsqrtf(g_deg[i]);
}

// ---------------- GEMM with fused BN-apply (input) + agg-init (epilogue) -----
// Block: 256 threads, 64 rows x 128 cols, full K=128 in smem.
// mode 0: X = raw input.  mode 1: X = relu(g_agg*scale + shift) on load.
// Epilogue: g_hW[r] = acc ; g_agg[r] = acc * dis[r]^2 (self-loop init; bias
// dropped — BN makes a per-feature constant shift a no-op).
__global__ void k_gemm(const float* __restrict__ Xin,
                       const float* __restrict__ W,
                       int mode)
{
    extern __shared__ float sm[];
    float* ws = sm;            // [128][128]
    float* xs = sm + 16384;    // [64][128]

    int tid  = threadIdx.x;
    int row0 = blockIdx.x * 64;

    const float4* W4  = (const float4*)W;
    float4*       ws4 = (float4*)ws;
#pragma unroll 4
    for (int t = tid; t < 4096; t += 256) ws4[t] = W4[t];

    const float4* X4 = mode ? (const float4*)g_agg : (const float4*)Xin;
    float4*      xs4 = (float4*)xs;
#pragma unroll 2
    for (int t = tid; t < 2048; t += 256) {
        int r = row0 + (t >> 5);
        int c = t & 31;
        float4 v = (r < Nn) ? X4[(size_t)r * 32 + c]
                            : make_float4(0.f, 0.f, 0.f, 0.f);
        if (mode) {
            float4 sc = ((const float4*)g_scale)[c];
            float4 sh = ((const float4*)g_shift)[c];
            v.x = fmaxf(fmaf(v.x, sc.x, sh.x), 0.f);
            v.y = fmaxf(fmaf(v.y, sc.y, sh.y), 0.f);
            v.z = fmaxf(fmaf(v.z, sc.z, sh.z), 0.f);
            v.w = fmaxf(fmaf(v.w, sc.w, sh.w), 0.f);
        }
        xs4[t] = v;
    }
    __syncthreads();

    int c0   = (tid & 31) * 4;   // column group (lane)
    int slot = tid >> 5;         // row slot 0..7

    float acc[8][4];
#pragma unroll
    for (int j = 0; j < 8; j++)
#pragma unroll
        for (int q = 0; q < 4; q++) acc[j][q] = 0.f;

    const float* xbase = xs + slot * 8 * 128;
#pragma unroll 2
    for (int k = 0; k < 128; k++) {
        float4 wv = *(const float4*)(ws + k * 128 + c0);
#pragma unroll
        for (int j = 0; j < 8; j++) {
            float xv = xbase[j * 128 + k];
            acc[j][0] = fmaf(xv, wv.x, acc[j][0]);
            acc[j][1] = fmaf(xv, wv.y, acc[j][1]);
            acc[j][2] = fmaf(xv, wv.z, acc[j][2]);
            acc[j][3] = fmaf(xv, wv.w, acc[j][3]);
        }
    }

    float4* Y4 = (float4*)g_hW;
    float4* A4 = (float4*)g_agg;
#pragma unroll
    for (int j = 0; j < 8; j++) {
        int r = row0 + slot * 8 + j;
        if (r < Nn) {
            float d = g_dis[r]; d *= d;
            float4 y = make_float4(acc[j][0], acc[j][1], acc[j][2], acc[j][3]);
            Y4[(size_t)r * 32 + (tid & 31)] = y;
            A4[(size_t)r * 32 + (tid & 31)] =
                make_float4(y.x * d, y.y * d, y.z * d, y.w * d);
        }
    }
}

// ---------------- edge scatter (dominant kernel) ------------------------------
// one warp per edge; lane handles 4 features; single v4 reduction per lane
__global__ void k_agg_edges() {
    int t = blockIdx.x * blockDim.x + threadIdx.x;
    int e = t >> 5;
    if (e >= Ee) return;
    int lane = t & 31;
    int s = g_src[e], d = g_dst[e];
    float nr = g_dis[s] * g_dis[d];
    float4 v = ((const float4*)g_hW)[(size_t)s * 32 + lane];
    float4* o = (float4*)&g_agg[(size_t)d * 128 + lane * 4];
    asm volatile("red.global.add.v4.f32 [%0], {%1, %2, %3, %4};"
                 :: "l"(o), "f"(v.x * nr), "f"(v.y * nr),
                    "f"(v.z * nr), "f"(v.w * nr)
                 : "memory");
}

// ---------------- batchnorm stats ---------------------------------------------
__global__ void k_bn_zero() {
    int f = threadIdx.x;
    g_sum[f] = 0.f; g_sumsq[f] = 0.f;
}

__global__ void k_bn_reduce() {
    int f  = threadIdx.x;              // 128 threads = features
    int r0 = blockIdx.x * 256;
    int r1 = min(r0 + 256, Nn);
    float s = 0.f, ss = 0.f;
    for (int r = r0; r < r1; r++) {
        float v = g_agg[(size_t)r * 128 + f];
        s += v; ss = fmaf(v, v, ss);
    }
    atomicAdd(&g_sum[f], s);
    atomicAdd(&g_sumsq[f], ss);
}

__global__ void k_bn_final(const float* __restrict__ gam,
                           const float* __restrict__ bet) {
    int f = threadIdx.x;
    float mu  = g_sum[f]   * (1.0f / Nn);
    float var = g_sumsq[f] * (1.0f / Nn) - mu * mu;
    float inv = rsqrtf(var + EPSf);
    float sc  = gam[f] * inv;
    g_scale[f] = sc;
    g_shift[f] = bet[f] - mu * sc;
}

// ---------------- pooling (fused BN-apply+ReLU) + classifier ------------------
__global__ void k_pool_zero() {
    int i = blockIdx.x * blockDim.x + threadIdx.x;
    if (i < Gg * Hh) g_pool[i] = 0.f;
}

// batch is sorted: accumulate in registers, flush on graph change
__global__ void k_pool() {
    int f  = threadIdx.x;              // 128 threads = features
    int r0 = blockIdx.x * 256;
    if (r0 >= Nn) return;
    int r1 = min(r0 + 256, Nn);
    float sc = g_scale[f], sh = g_shift[f];
    int cur = g_batch[r0];
    float acc = 0.f;
    for (int r = r0; r < r1; r++) {
        int bg = g_batch[r];
        if (bg != cur) {
            atomicAdd(&g_pool[cur * 128 + f], acc);
            acc = 0.f; cur = bg;
        }
        float v = g_agg[(size_t)r * 128 + f];
        acc += fmaxf(fmaf(v, sc, sh), 0.f);
    }
    atomicAdd(&g_pool[cur * 128 + f], acc);
}

__global__ void k_classify(const float* __restrict__ Wc,
                           const float* __restrict__ bc,
                           float* __restrict__ out) {
    int g = blockIdx.x;
    int c = threadIdx.x;
    if (c >= Cc) return;
    float a = bc[c];
#pragma unroll 4
    for (int f = 0; f < 128; f++)
        a = fmaf(g_pool[g * 128 + f], Wc[f * Cc + c], a);
    out[g * Cc + c] = a;
}

// ---------------- launch ------------------------------------------------------
extern "C" void kernel_launch(void* const* d_in, const int* in_sizes, int n_in,
                              void* d_out, int out_size) {
    const float* x     = (const float*)d_in[0];
    const int*   ei_w  = (const int*)  d_in[1];   // word view (int32 or int64)
    const int*   bat_w = (const int*)  d_in[2];
    const float* W[3]  = { (const float*)d_in[3],  (const float*)d_in[7],  (const float*)d_in[11] };
    const float* ga[3] = { (const float*)d_in[5],  (const float*)d_in[9],  (const float*)d_in[13] };
    const float* be[3] = { (const float*)d_in[6],  (const float*)d_in[10], (const float*)d_in[14] };
    const float* Wc    = (const float*)d_in[15];
    const float* bc    = (const float*)d_in[16];
    float*       out   = (float*)d_out;

    cudaFuncSetAttribute(k_gemm, cudaFuncAttributeMaxDynamicSharedMemorySize, 98304);

    k_detect   <<<1, 32>>>(ei_w, bat_w);
    k_cvt_edges<<<(Ee + 255) / 256, 256>>>(ei_w);
    k_cvt_batch<<<(Nn + 255) / 256, 256>>>(bat_w);

    k_init_deg <<<(Nn + 255) / 256, 256>>>();
    k_count_deg<<<(Ee + 255) / 256, 256>>>();
    k_dis      <<<(Nn + 255) / 256, 256>>>();

    for (int l = 0; l < 3; l++) {
        k_gemm     <<<(Nn + 63) / 64, 256, 98304>>>(x, W[l], l == 0 ? 0 : 1);
        k_agg_edges<<<(int)(((size_t)Ee * 32 + 255) / 256), 256>>>();
        k_bn_zero  <<<1, 128>>>();
        k_bn_reduce<<<(Nn + 255) / 256, 128>>>();
        k_bn_final <<<1, 128>>>(ga[l], be[l]);
    }

    k_pool_zero<<<(Gg * Hh + 255) / 256, 256>>>();
    k_pool     <<<(Nn + 255) / 256, 128>>>();
    k_classify <<<Gg, 32>>>(Wc, bc, out);
}

// round 15
// speedup vs baseline: 1.2883x; 1.2883x over previous
#include <cuda_runtime.h>
#include <cuda_bf16.h>
#include <mma.h>

#define Nn 100000
#define NnPad 100096   // Nn rounded up to 128 (GEMM tile rows)
#define Ee 1600000
#define Gg 128
#define Hh 128
#define Cc 10
#define EPSf 1e-5f
#define NBLK 391   // ceil(Nn/256)

using namespace nvcuda;

// ---------------- scratch (device globals; no allocations allowed) -----------
// __align__(16): these arrays are accessed via float4/uint4 casts; element-type
// alignment alone (2B/4B) is NOT guaranteed to be 16B for __device__ arrays.
__device__ __align__(16) float g_dis[Nn];
__device__ __align__(16) float g_hW [NnPad * Hh];  // dis[row] * (h @ W)
__device__ __align__(16) float g_agg[NnPad * Hh];  // aggregated messages (pre-BN)
__device__ __align__(16) __nv_bfloat16 g_Whi[Hh * Hh];
__device__ __align__(16) __nv_bfloat16 g_Wlo[Hh * Hh];
__device__ __align__(16) float g_sum[Hh];
__device__ __align__(16) float g_sumsq[Hh];
__device__ __align__(16) float g_scale[Hh];
__device__ __align__(16) float g_shift[Hh];
__device__ __align__(16) float g_pool[Gg * Hh];
__device__ int   g_src[Ee];
__device__ int   g_dst[Ee];
__device__ int   g_batch[Nn];
__device__ int   g_flag[2];        // [0]: edge_index int64?, [1]: batch int64?
__device__ int   g_degi[Nn];       // in-degree (edges only)
__device__ int   g_rowstart[Nn];   // CSR row starts (by dst)
__device__ int   g_bsum[NBLK + 1];
__device__ int   g_cur[Nn];
__device__ int   g_csrc[Ee];       // CSR column (src) ids

// ---------------- dtype detection + canonicalization -------------------------
// int64 buffers with small non-negative values have every odd 32-bit word == 0.
// Samples stay within the int32-sized footprint (safe either way).
__global__ void k_detect(const int* __restrict__ ei_w, const int* __restrict__ b_w) {
    if (threadIdx.x != 0) return;
    int all0 = 1;
    for (int i = 0; i < 16; i++)
        if (ei_w[2 * Ee - 1 - 2 * i] != 0) { all0 = 0; break; }
    g_flag[0] = all0;
    all0 = 1;
    for (int i = 0; i < 16; i++)
        if (b_w[Nn - 1 - 2 * i] != 0) { all0 = 0; break; }
    g_flag[1] = all0;
}

__global__ void k_zero_int() {
    int i = blockIdx.x * blockDim.x + threadIdx.x;
    if (i < Nn) { g_degi[i] = 0; g_cur[i] = 0; }
}

// convert edges to int32 + fused dst histogram
__global__ void k_cvt_edges(const int* __restrict__ w) {
    int e = blockIdx.x * blockDim.x + threadIdx.x;
    if (e >= Ee) return;
    int s, d;
    if (g_flag[0]) { s = w[2 * e]; d = w[2 * Ee + 2 * e]; }
    else           { s = w[e];     d = w[Ee + e]; }
    g_src[e] = s;
    g_dst[e] = d;
    atomicAdd(&g_degi[d], 1);
}

__global__ void k_cvt_batch(const int* __restrict__ w) {
    int i = blockIdx.x * blockDim.x + threadIdx.x;
    if (i >= Nn) return;
    g_batch[i] = g_flag[1] ? w[2 * i] : w[i];
}

// ---------------- CSR build: exclusive scan of degrees ------------------------
__global__ void k_scanA() {
    __shared__ int s[256];
    int i = blockIdx.x * 256 + threadIdx.x;
    int v = (i < Nn) ? g_degi[i] : 0;
    s[threadIdx.x] = v;
    __syncthreads();
#pragma unroll
    for (int off = 1; off < 256; off <<= 1) {
        int t = (threadIdx.x >= off) ? s[threadIdx.x - off] : 0;
        __syncthreads();
        s[threadIdx.x] += t;
        __syncthreads();
    }
    if (i < Nn) g_rowstart[i] = s[threadIdx.x] - v;   // block-local exclusive
    if (threadIdx.x == 255) g_bsum[blockIdx.x] = s[255];
}

__global__ void k_scanB() {
    if (threadIdx.x != 0) return;
    int a = 0;
    for (int b = 0; b < NBLK; b++) { int t = g_bsum[b]; g_bsum[b] = a; a += t; }
}

__global__ void k_scanC() {
    int i = blockIdx.x * blockDim.x + threadIdx.x;
    if (i < Nn) {
        g_rowstart[i] += g_bsum[i >> 8];
        g_dis[i] = rsqrtf(1.0f + (float)g_degi[i]);   // +1 self-loop
    }
}

__global__ void k_fill() {
    int e = blockIdx.x * blockDim.x + threadIdx.x;
    if (e >= Ee) return;
    int d = g_dst[e];
    int pos = g_rowstart[d] + atomicAdd(&g_cur[d], 1);
    g_csrc[pos] = g_src[e];
}

// ---------------- per-layer W -> bf16 hi/lo -----------------------------------
__global__ void k_cvtW(const float* __restrict__ W) {
    int i = blockIdx.x * blockDim.x + threadIdx.x;
    if (i >= Hh * Hh) return;
    float v = W[i];
    __nv_bfloat16 h = __float2bfloat16(v);
    g_Whi[i] = h;
    g_Wlo[i] = __float2bfloat16(v - __bfloat162float(h));
}

// ---------------- GEMM: bf16 hi/lo split on tensor cores ----------------------
// Block: 256 threads (8 warps), 128-row x 128-col tile, full K=128.
// X rows pre-scaled by dis[row] on load (row scaling commutes with GEMM), so
// accumulators are stored DIRECTLY to g_hW (padded) — no epilogue pass.
// acc = Ah*Wh + Ah*Wl + Al*Wh in fp32; dropped lo*lo term ~2^-18 relative.
// mode 0: X = raw input.  mode 1: X = relu(g_agg*scale + shift) on load.
// Bias dropped (no-op under BatchNorm). Block 0 zeroes BN accumulators.
__global__ void __launch_bounds__(256, 1) k_gemm(const float* __restrict__ Xin, int mode)
{
    extern __shared__ char smraw[];
    __nv_bfloat16* aHi = (__nv_bfloat16*)(smraw);            // [128][128]
    __nv_bfloat16* aLo = (__nv_bfloat16*)(smraw + 32768);
    __nv_bfloat16* wHi = (__nv_bfloat16*)(smraw + 65536);
    __nv_bfloat16* wLo = (__nv_bfloat16*)(smraw + 98304);

    int tid  = threadIdx.x;
    int wid  = tid >> 5;
    int row0 = blockIdx.x * 128;

    if (blockIdx.x == 0 && tid < 128) { g_sum[tid] = 0.f; g_sumsq[tid] = 0.f; }

    // W hi/lo: straight bf16 copy from global (L2-resident)
    const uint4* whi4 = (const uint4*)g_Whi;
    const uint4* wlo4 = (const uint4*)g_Wlo;
    uint4* swhi = (uint4*)wHi;
    uint4* swlo = (uint4*)wLo;
#pragma unroll 4
    for (int t = tid; t < 2048; t += 256) { swhi[t] = whi4[t]; swlo[t] = wlo4[t]; }

    // X (optionally BN+ReLU), scaled by dis[row] -> hi/lo bf16
    const float4* X4 = mode ? (const float4*)g_agg : (const float4*)Xin;
#pragma unroll 4
    for (int t = tid; t < 4096; t += 256) {
        int r = t >> 5;
        int c = t & 31;
        int gr = row0 + r;
        float4 v = (gr < Nn) ? X4[(size_t)gr * 32 + c]
                             : make_float4(0.f, 0.f, 0.f, 0.f);
        if (mode) {
            float4 sc = ((const float4*)g_scale)[c];
            float4 sh = ((const float4*)g_shift)[c];
            v.x = fmaxf(fmaf(v.x, sc.x, sh.x), 0.f);
            v.y = fmaxf(fmaf(v.y, sc.y, sh.y), 0.f);
            v.z = fmaxf(fmaf(v.z, sc.z, sh.z), 0.f);
            v.w = fmaxf(fmaf(v.w, sc.w, sh.w), 0.f);
        }
        float dsc = (gr < Nn) ? g_dis[gr] : 0.f;
        v.x *= dsc; v.y *= dsc; v.z *= dsc; v.w *= dsc;
        int base = r * 128 + c * 4;
        __nv_bfloat16 hx = __float2bfloat16(v.x);
        __nv_bfloat16 hy = __float2bfloat16(v.y);
        __nv_bfloat16 hz = __float2bfloat16(v.z);
        __nv_bfloat16 hw = __float2bfloat16(v.w);
        aHi[base + 0] = hx; aLo[base + 0] = __float2bfloat16(v.x - __bfloat162float(hx));
        aHi[base + 1] = hy; aLo[base + 1] = __float2bfloat16(v.y - __bfloat162float(hy));
        aHi[base + 2] = hz; aLo[base + 2] = __float2bfloat16(v.z - __bfloat162float(hz));
        aHi[base + 3] = hw; aLo[base + 3] = __float2bfloat16(v.w - __bfloat162float(hw));
    }
    __syncthreads();

    // wmma: each warp owns a 16-row stripe x 128 cols (8 acc tiles)
    wmma::fragment<wmma::accumulator, 16, 16, 16, float> acc[8];
#pragma unroll
    for (int n = 0; n < 8; n++) wmma::fill_fragment(acc[n], 0.f);

#pragma unroll
    for (int k0 = 0; k0 < 8; k0++) {
        wmma::fragment<wmma::matrix_a, 16, 16, 16, __nv_bfloat16, wmma::row_major> ah, al;
        wmma::load_matrix_sync(ah, aHi + (wid * 16) * 128 + k0 * 16, 128);
        wmma::load_matrix_sync(al, aLo + (wid * 16) * 128 + k0 * 16, 128);
#pragma unroll
        for (int n = 0; n < 8; n++) {
            wmma::fragment<wmma::matrix_b, 16, 16, 16, __nv_bfloat16, wmma::row_major> bh, bl;
            wmma::load_matrix_sync(bh, wHi + (k0 * 16) * 128 + n * 16, 128);
            wmma::load_matrix_sync(bl, wLo + (k0 * 16) * 128 + n * 16, 128);
            wmma::mma_sync(acc[n], ah, bh, acc[n]);
            wmma::mma_sync(acc[n], ah, bl, acc[n]);
            wmma::mma_sync(acc[n], al, bh, acc[n]);
        }
    }

    // store directly to (padded) global
    float* yb = g_hW + (size_t)(row0 + wid * 16) * 128;
#pragma unroll
    for (int n = 0; n < 8; n++)
        wmma::store_matrix_sync(yb + n * 16, acc[n], 128, wmma::mem_row_major);
}

// ---------------- CSR aggregation (no atomics) --------------------------------
// One warp per dst node. hW is pre-scaled by dis[src], so:
//   agg[d] = (hW[d] + sum_{s in row(d)} hW[s]) * dis[d]
__global__ void k_agg_csr() {
    int w = (blockIdx.x * blockDim.x + threadIdx.x) >> 5;   // node id
    if (w >= Nn) return;
    int lane  = threadIdx.x & 31;
    int start = __ldg(&g_rowstart[w]);
    int cnt   = __ldg(&g_degi[w]);

    const float4* H4 = (const float4*)g_hW;
    float4 acc = H4[(size_t)w * 32 + lane];                 // self-loop term

    int j = 0;
    for (; j + 4 <= cnt; j += 4) {
        int s0 = __ldg(&g_csrc[start + j]);
        int s1 = __ldg(&g_csrc[start + j + 1]);
        int s2 = __ldg(&g_csrc[start + j + 2]);
        int s3 = __ldg(&g_csrc[start + j + 3]);
        float4 v0 = H4[(size_t)s0 * 32 + lane];
        float4 v1 = H4[(size_t)s1 * 32 + lane];
        float4 v2 = H4[(size_t)s2 * 32 + lane];
        float4 v3 = H4[(size_t)s3 * 32 + lane];
        acc.x += (v0.x + v1.x) + (v2.x + v3.x);
        acc.y += (v0.y + v1.y) + (v2.y + v3.y);
        acc.z += (v0.z + v1.z) + (v2.z + v3.z);
        acc.w += (v0.w + v1.w) + (v2.w + v3.w);
    }
    for (; j < cnt; j++) {
        int s = __ldg(&g_csrc[start + j]);
        float4 v = H4[(size_t)s * 32 + lane];
        acc.x += v.x; acc.y += v.y; acc.z += v.z; acc.w += v.w;
    }

    float dd = g_dis[w];
    acc.x *= dd; acc.y *= dd; acc.z *= dd; acc.w *= dd;
    ((float4*)g_agg)[(size_t)w * 32 + lane] = acc;
}

// ---------------- batchnorm stats ---------------------------------------------
__global__ void k_bn_reduce() {
    int f  = threadIdx.x;              // 128 threads = features
    int r0 = blockIdx.x * 256;
    int r1 = min(r0 + 256, Nn);
    float s = 0.f, ss = 0.f;
    for (int r = r0; r < r1; r++) {
        float v = __ldg(&g_agg[(size_t)r * 128 + f]);
        s += v; ss = fmaf(v, v, ss);
    }
    atomicAdd(&g_sum[f], s);
    atomicAdd(&g_sumsq[f], ss);
}

__global__ void k_bn_final(const float* __restrict__ gam,
                           const float* __restrict__ bet) {
    int f = threadIdx.x;
    float mu  = g_sum[f]   * (1.0f / Nn);
    float var = g_sumsq[f] * (1.0f / Nn) - mu * mu;
    float inv = rsqrtf(var + EPSf);
    float sc  = gam[f] * inv;
    g_scale[f] = sc;
    g_shift[f] = bet[f] - mu * sc;
}

// ---------------- pooling (fused BN-apply+ReLU) + classifier ------------------
__global__ void k_pool_zero() {
    int i = blockIdx.x * blockDim.x + threadIdx.x;
    if (i < Gg * Hh) g_pool[i] = 0.f;
}

// batch is sorted: accumulate in registers, flush on graph change
__global__ void k_pool() {
    int f  = threadIdx.x;              // 128 threads = features
    int r0 = blockIdx.x * 256;
    if (r0 >= Nn) return;
    int r1 = min(r0 + 256, Nn);
    float sc = g_scale[f], sh = g_shift[f];
    int cur = g_batch[r0];
    float acc = 0.f;
    for (int r = r0; r < r1; r++) {
        int bg = g_batch[r];
        if (bg != cur) {
            atomicAdd(&g_pool[cur * 128 + f], acc);
            acc = 0.f; cur = bg;
        }
        float v = g_agg[(size_t)r * 128 + f];
        acc += fmaxf(fmaf(v, sc, sh), 0.f);
    }
    atomicAdd(&g_pool[cur * 128 + f], acc);
}

__global__ void k_classify(const float* __restrict__ Wc,
                           const float* __restrict__ bc,
                           float* __restrict__ out) {
    int g = blockIdx.x;
    int c = threadIdx.x;
    if (c >= Cc) return;
    float a = bc[c];
#pragma unroll 4
    for (int f = 0; f < 128; f++)
        a = fmaf(g_pool[g * 128 + f], Wc[f * Cc + c], a);
    out[g * Cc + c] = a;
}

// ---------------- launch ------------------------------------------------------
extern "C" void kernel_launch(void* const* d_in, const int* in_sizes, int n_in,
                              void* d_out, int out_size) {
    const float* x     = (const float*)d_in[0];
    const int*   ei_w  = (const int*)  d_in[1];
    const int*   bat_w = (const int*)  d_in[2];
    const float* W[3]  = { (const float*)d_in[3],  (const float*)d_in[7],  (const float*)d_in[11] };
    const float* ga[3] = { (const float*)d_in[5],  (const float*)d_in[9],  (const float*)d_in[13] };
    const float* be[3] = { (const float*)d_in[6],  (const float*)d_in[10], (const float*)d_in[14] };
    const float* Wc    = (const float*)d_in[15];
    const float* bc    = (const float*)d_in[16];
    float*       out   = (float*)d_out;

    cudaFuncSetAttribute(k_gemm, cudaFuncAttributeMaxDynamicSharedMemorySize, 131072);

    // graph preprocessing (once per launch)
    k_detect   <<<1, 32>>>(ei_w, bat_w);
    k_zero_int <<<(Nn + 255) / 256, 256>>>();
    k_cvt_edges<<<(Ee + 255) / 256, 256>>>(ei_w);
    k_cvt_batch<<<(Nn + 255) / 256, 256>>>(bat_w);
    k_scanA    <<<NBLK, 256>>>();
    k_scanB    <<<1, 32>>>();
    k_scanC    <<<(Nn + 255) / 256, 256>>>();
    k_fill     <<<(Ee + 255) / 256, 256>>>();

    for (int l = 0; l < 3; l++) {
        k_cvtW     <<<(Hh * Hh + 255) / 256, 256>>>(W[l]);
        k_gemm     <<<NnPad / 128, 256, 131072>>>(x, l == 0 ? 0 : 1);
        k_agg_csr  <<<(Nn * 32 + 255) / 256, 256>>>();
        k_bn_reduce<<<(Nn + 255) / 256, 128>>>();
        k_bn_final <<<1, 128>>>(ga[l], be[l]);
    }

    k_pool_zero<<<(Gg * Hh + 255) / 256, 256>>>();
    k_pool     <<<(Nn + 255) / 256, 128>>>();
    k_classify <<<Gg, 32>>>(Wc, bc, out);
}